// round 2
// baseline (speedup 1.0000x reference)
#include <cuda_runtime.h>

typedef unsigned long long ull;

// ---------------- dimensions ----------------
static constexpr int DA = 45, DB = 102, DM = 4, DH = 68;

// ---------------- shared-memory layout (floats), all offsets even ----------------
static constexpr int OFF_Wa = 0;                      // 45*68
static constexpr int OFF_ba = OFF_Wa + 45 * 68;       // 3060
static constexpr int OFF_Wb = OFF_ba + 68;            // 3128
static constexpr int OFF_bb = OFF_Wb + 102 * 68;      // 10064
static constexpr int OFF_W0 = OFF_bb + 68;            // 10132 (140x34)
static constexpr int OFF_B0 = OFF_W0 + 140 * 34;      // 14892
static constexpr int OFF_W1 = OFF_B0 + 34;            // (34x34)
static constexpr int OFF_B1 = OFF_W1 + 34 * 34;
static constexpr int OFF_W2 = OFF_B1 + 34;            // (34x20)
static constexpr int OFF_B2 = OFF_W2 + 34 * 20;
static constexpr int OFF_W3 = OFF_B2 + 20;            // (20x20)
static constexpr int OFF_B3 = OFF_W3 + 400;
static constexpr int OFF_W4 = OFF_B3 + 20;
static constexpr int OFF_B4 = OFF_W4 + 400;
static constexpr int OFF_W5 = OFF_B4 + 20;
static constexpr int OFF_B5 = OFF_W5 + 400;
static constexpr int OFF_W6 = OFF_B5 + 20;
static constexpr int OFF_B6 = OFF_W6 + 400;
static constexpr int OFF_W7 = OFF_B6 + 20;            // 20x6 (padded from 20x5)
static constexpr int OFF_B7 = OFF_W7 + 20 * 6;        // 6 (padded from 5)
static constexpr int OFF_W8 = OFF_B7 + 6;             // 5x2
static constexpr int OFF_B8 = OFF_W8 + 10;            // 2
static constexpr int OFF_W9 = OFF_B8 + 2;             // 2x2 (padded from 2x1)
static constexpr int OFF_B9 = OFF_W9 + 4;             // 2 (padded from 1)
static constexpr int SMEM_FLOATS = OFF_B9 + 2;        // 18640
static constexpr int SMEM_BYTES = SMEM_FLOATS * 4;    // 74560

// ---------------- f32x2 helpers (Blackwell packed fp32, PTX-only) ----------------
__device__ __forceinline__ ull pack2(float x, float y) {
    ull r; asm("mov.b64 %0, {%1, %2};" : "=l"(r) : "f"(x), "f"(y)); return r;
}
__device__ __forceinline__ void unpack2(ull v, float& x, float& y) {
    asm("mov.b64 {%0, %1}, %2;" : "=f"(x), "=f"(y) : "l"(v));
}
__device__ __forceinline__ ull ffma2(ull a, ull b, ull c) {
    ull d; asm("fma.rn.f32x2 %0, %1, %2, %3;" : "=l"(d) : "l"(a), "l"(b), "l"(c)); return d;
}
__device__ __forceinline__ float lrelu(float x) { return fmaxf(x, 0.01f * x); }

// ---------------- smem staging ----------------
__device__ __forceinline__ void cp(float* __restrict__ s, const float* __restrict__ g,
                                   int n, int tid, int nt) {
    for (int i = tid; i < n; i += nt) s[i] = g[i];
}
__device__ __forceinline__ void cppad(float* __restrict__ s, const float* __restrict__ g,
                                      int K, int N, int NP, int tid, int nt) {
    for (int i = tid; i < K * NP; i += nt) {
        int r = i / NP, c = i - r * NP;
        s[i] = (c < N) ? g[r * N + c] : 0.0f;
    }
}

// Feed one concat-activation value (index k in [0,140)) into the 34-wide layer-0
// accumulator. This fuses towers->layer0 so the 140-wide concat never lives in regs.
__device__ __forceinline__ void feed0(float v, int k, const ull* __restrict__ w64,
                                      ull (&acc0)[17]) {
    ull xs = pack2(v, v);
    const int base = (OFF_W0 >> 1) + k * 17;
#pragma unroll
    for (int p = 0; p < 17; p++) acc0[p] = ffma2(xs, w64[base + p], acc0[p]);
}

// Input tower: streams row x[0..K) from global, 68-wide GEMV (34 f32x2 accs),
// LeakyReLU, then feeds each output straight into acc0 at concat offset cbase.
template <int K>
__device__ __forceinline__ void tower(const float* __restrict__ x,
                                      const ull* __restrict__ w64,
                                      int woff, int boff, int cbase,
                                      ull (&acc0)[17]) {
    ull acc[34];
#pragma unroll
    for (int p = 0; p < 34; p++) acc[p] = w64[(boff >> 1) + p];
#pragma unroll 3
    for (int k = 0; k < K; k++) {
        float xk = __ldg(x + k);
        ull xs = pack2(xk, xk);
        const int base = (woff >> 1) + k * 34;
#pragma unroll
        for (int p = 0; p < 34; p++) acc[p] = ffma2(xs, w64[base + p], acc[p]);
    }
#pragma unroll
    for (int p = 0; p < 34; p++) {
        float v0, v1; unpack2(acc[p], v0, v1);
        feed0(lrelu(v0), cbase + 2 * p + 0, w64, acc0);
        feed0(lrelu(v1), cbase + 2 * p + 1, w64, acc0);
    }
}

// Dense layer on register-resident input. NP = output dim padded to even.
template <int K, int NP, int IN>
__device__ __forceinline__ void dense(const float (&in)[IN], float (&out)[NP],
                                      const ull* __restrict__ w64, int woff, int boff) {
    static_assert(IN >= K, "input too small");
    constexpr int P = NP / 2;
    ull acc[P];
#pragma unroll
    for (int p = 0; p < P; p++) acc[p] = w64[(boff >> 1) + p];
#pragma unroll
    for (int k = 0; k < K; k++) {
        ull xs = pack2(in[k], in[k]);
        const int base = (woff >> 1) + k * P;
#pragma unroll
        for (int p = 0; p < P; p++) acc[p] = ffma2(xs, w64[base + p], acc[p]);
    }
#pragma unroll
    for (int p = 0; p < P; p++) {
        float v0, v1; unpack2(acc[p], v0, v1);
        out[2 * p + 0] = lrelu(v0);
        out[2 * p + 1] = lrelu(v1);
    }
}

__global__ __launch_bounds__(256, 1)
void Net_67954972557347_kernel(
    const float* __restrict__ a, const float* __restrict__ b, const float* __restrict__ meta,
    const float* __restrict__ Wa, const float* __restrict__ ba,
    const float* __restrict__ Wb, const float* __restrict__ bb,
    const float* __restrict__ W0, const float* __restrict__ B0,
    const float* __restrict__ W1, const float* __restrict__ B1,
    const float* __restrict__ W2, const float* __restrict__ B2,
    const float* __restrict__ W3, const float* __restrict__ B3,
    const float* __restrict__ W4, const float* __restrict__ B4,
    const float* __restrict__ W5, const float* __restrict__ B5,
    const float* __restrict__ W6, const float* __restrict__ B6,
    const float* __restrict__ W7, const float* __restrict__ B7,
    const float* __restrict__ W8, const float* __restrict__ B8,
    const float* __restrict__ W9, const float* __restrict__ B9,
    float* __restrict__ outp, int nrows)
{
    extern __shared__ float sm[];
    const int tid = threadIdx.x, nt = blockDim.x;

    // Stage all weights/biases into shared (odd N padded to even for aligned LDS.64).
    cp(sm + OFF_Wa, Wa, 45 * 68, tid, nt);
    cp(sm + OFF_ba, ba, 68, tid, nt);
    cp(sm + OFF_Wb, Wb, 102 * 68, tid, nt);
    cp(sm + OFF_bb, bb, 68, tid, nt);
    cp(sm + OFF_W0, W0, 140 * 34, tid, nt);
    cp(sm + OFF_B0, B0, 34, tid, nt);
    cp(sm + OFF_W1, W1, 34 * 34, tid, nt);
    cp(sm + OFF_B1, B1, 34, tid, nt);
    cp(sm + OFF_W2, W2, 34 * 20, tid, nt);
    cp(sm + OFF_B2, B2, 20, tid, nt);
    cp(sm + OFF_W3, W3, 400, tid, nt);
    cp(sm + OFF_B3, B3, 20, tid, nt);
    cp(sm + OFF_W4, W4, 400, tid, nt);
    cp(sm + OFF_B4, B4, 20, tid, nt);
    cp(sm + OFF_W5, W5, 400, tid, nt);
    cp(sm + OFF_B5, B5, 20, tid, nt);
    cp(sm + OFF_W6, W6, 400, tid, nt);
    cp(sm + OFF_B6, B6, 20, tid, nt);
    cppad(sm + OFF_W7, W7, 20, 5, 6, tid, nt);
    cppad(sm + OFF_B7, B7, 1, 5, 6, tid, nt);
    cp(sm + OFF_W8, W8, 10, tid, nt);
    cp(sm + OFF_B8, B8, 2, tid, nt);
    cppad(sm + OFF_W9, W9, 2, 1, 2, tid, nt);
    cppad(sm + OFF_B9, B9, 1, 1, 2, tid, nt);
    __syncthreads();

    const ull* w64 = reinterpret_cast<const ull*>(sm);
    const int stride = gridDim.x * blockDim.x;

    for (int row = blockIdx.x * blockDim.x + tid; row < nrows; row += stride) {
        // layer-0 accumulator, bias-initialized; towers feed it directly
        ull acc0[17];
#pragma unroll
        for (int p = 0; p < 17; p++) acc0[p] = w64[(OFF_B0 >> 1) + p];

        tower<DA>(a + (size_t)row * DA, w64, OFF_Wa, OFF_ba, 0, acc0);
        tower<DB>(b + (size_t)row * DB, w64, OFF_Wb, OFF_bb, DH, acc0);
        const float* mrow = meta + (size_t)row * DM;
#pragma unroll
        for (int i = 0; i < DM; i++) feed0(__ldg(mrow + i), 2 * DH + i, w64, acc0);  // meta: no lrelu

        float c1[34];
#pragma unroll
        for (int p = 0; p < 17; p++) {
            float v0, v1; unpack2(acc0[p], v0, v1);
            c1[2 * p + 0] = lrelu(v0);
            c1[2 * p + 1] = lrelu(v1);
        }

        float c2[34]; dense<34, 34>(c1, c2, w64, OFF_W1, OFF_B1);
        float c3[20]; dense<34, 20>(c2, c3, w64, OFF_W2, OFF_B2);
        float c4[20]; dense<20, 20>(c3, c4, w64, OFF_W3, OFF_B3);
        float c5[20]; dense<20, 20>(c4, c5, w64, OFF_W4, OFF_B4);
        float c6[20]; dense<20, 20>(c5, c6, w64, OFF_W5, OFF_B5);
        float c7[20]; dense<20, 20>(c6, c7, w64, OFF_W6, OFF_B6);
        float c8[6];  dense<20, 6>(c7, c8, w64, OFF_W7, OFF_B7);   // true dim 5, lane 5 = lrelu(0)=0
        float c9[2];  dense<5, 2>(c8, c9, w64, OFF_W8, OFF_B8);

        // final 2 -> 1 (scalar, W9 padded to stride 2)
        float o = fmaf(c9[0], sm[OFF_W9 + 0], fmaf(c9[1], sm[OFF_W9 + 2], sm[OFF_B9]));
        outp[row] = lrelu(o);
    }
}

extern "C" void kernel_launch(void* const* d_in, const int* in_sizes, int n_in,
                              void* d_out, int out_size) {
    const float* a    = (const float*)d_in[0];
    const float* b    = (const float*)d_in[1];
    const float* meta = (const float*)d_in[2];
    const float* Wa   = (const float*)d_in[3];
    const float* ba   = (const float*)d_in[4];
    const float* Wb   = (const float*)d_in[5];
    const float* bb   = (const float*)d_in[6];
    const float* W[10], *Bb[10];
    for (int i = 0; i < 10; i++) {
        W[i]  = (const float*)d_in[7 + 2 * i];
        Bb[i] = (const float*)d_in[8 + 2 * i];
    }
    float* outp = (float*)d_out;
    const int nrows = in_sizes[0] / DA;

    cudaFuncSetAttribute(Net_67954972557347_kernel,
                         cudaFuncAttributeMaxDynamicSharedMemorySize, SMEM_BYTES);

    // 148 SMs on sm_100a; 1 block of 256 threads per SM, grid-stride over rows
    // (262144 / 37888 = 6.92 rows/thread -> well balanced).
    Net_67954972557347_kernel<<<148, 256, SMEM_BYTES>>>(
        a, b, meta, Wa, ba, Wb, bb,
        W[0], Bb[0], W[1], Bb[1], W[2], Bb[2], W[3], Bb[3], W[4], Bb[4],
        W[5], Bb[5], W[6], Bb[6], W[7], Bb[7], W[8], Bb[8], W[9], Bb[9],
        outp, nrows);
}